// round 3
// baseline (speedup 1.0000x reference)
#include <cuda_runtime.h>
#include <cstdint>
#include <cstddef>

#define HID 128
#define C3  384
#define TT  512
#define BB  4096
#define INP 28

// 3.2 GB scratch for precomputed input projections, consumer-friendly layout:
// gx[t][j][b][16] with j = c/16 (24 groups of 16 cols), 16 floats contiguous
// per (b, j). Split in two halves by t (each 1.6 GB).
__device__ __align__(16) float g_gx_lo[(size_t)256 * BB * C3];
__device__ __align__(16) float g_gx_hi[(size_t)256 * BB * C3];

// Packed dual-fp32 FMA (Blackwell f32x2: 2 MACs per 2-cyc slot → 128 MAC/cyc/SM).
static __device__ __forceinline__ float2 ffma2(float2 a, float2 b, float2 c) {
    unsigned long long ua, ub, uc, ud;
    ua = *reinterpret_cast<unsigned long long*>(&a);
    ub = *reinterpret_cast<unsigned long long*>(&b);
    uc = *reinterpret_cast<unsigned long long*>(&c);
    asm("fma.rn.f32x2 %0, %1, %2, %3;" : "=l"(ud) : "l"(ua), "l"(ub), "l"(uc));
    return *reinterpret_cast<float2*>(&ud);
}

static __device__ __forceinline__ float sig1(float x) {
    float e = __expf(-x);
    return __fdividef(1.0f, 1.0f + e);
}
static __device__ __forceinline__ float tanh1(float x) {
    float e = __expf(2.0f * x);
    return 1.0f - __fdividef(2.0f, e + 1.0f);
}

// ---------------------------------------------------------------------------
// Kernel A: gx[t][j][b][i] = sum_k x[b][t][k] * w_x[c/128][k][c%128] + b_x[c]
//           with c = 16*j + i.
// Block: one batch row b, 64 timesteps. 384 threads; thread = 16 t x 4 cols.
// ---------------------------------------------------------------------------
__global__ void __launch_bounds__(384)
gx_kernel(const float* __restrict__ x,
          const float* __restrict__ w_x,
          const float* __restrict__ b_x) {
    extern __shared__ float sm[];
    float* sXt = sm;            // [28][64]  transposed x
    float* sWx = sm + 64 * INP; // [28][384]

    const int b   = blockIdx.x;
    const int t0  = blockIdx.y * 64;
    const int tid = threadIdx.x;

    const float* xg = x + ((size_t)b * TT + t0) * INP;
    for (int idx = tid; idx < 64 * INP; idx += 384) {
        int tt = idx / INP, k = idx % INP;
        sXt[k * 64 + tt] = xg[idx];
    }
    for (int idx = tid; idx < INP * C3; idx += 384) {
        int k = idx / C3, c = idx % C3;
        sWx[idx] = w_x[(size_t)(c >> 7) * INP * HID + k * HID + (c & 127)];
    }
    __syncthreads();

    const int cg = tid % 96;   // cols 4cg .. 4cg+3
    const int rg = tid / 96;   // timesteps rg*16 .. rg*16+15

    float2 a[16][2];
#pragma unroll
    for (int r = 0; r < 16; ++r) {
        a[r][0] = make_float2(0.f, 0.f);
        a[r][1] = make_float2(0.f, 0.f);
    }

    const float* xp0 = sXt + rg * 16;
    const float* wp0 = sWx + 4 * cg;

#pragma unroll 4
    for (int k = 0; k < INP; ++k) {
        float4 wv = *(const float4*)(wp0 + k * C3);
        float2 w0 = make_float2(wv.x, wv.y);
        float2 w1 = make_float2(wv.z, wv.w);
        const float* xp = xp0 + k * 64;
        float4 xa = *(const float4*)(xp);
        float4 xb = *(const float4*)(xp + 4);
        float4 xc = *(const float4*)(xp + 8);
        float4 xd = *(const float4*)(xp + 12);
        float xs[16] = {xa.x, xa.y, xa.z, xa.w, xb.x, xb.y, xb.z, xb.w,
                        xc.x, xc.y, xc.z, xc.w, xd.x, xd.y, xd.z, xd.w};
#pragma unroll
        for (int r = 0; r < 16; ++r) {
            float2 xx = make_float2(xs[r], xs[r]);
            a[r][0] = ffma2(xx, w0, a[r][0]);
            a[r][1] = ffma2(xx, w1, a[r][1]);
        }
    }

    float2 bx0 = *(const float2*)(b_x + 4 * cg);
    float2 bx1 = *(const float2*)(b_x + 4 * cg + 2);
    const int c0 = 4 * cg;
    const int j  = c0 >> 4;     // 16-col group
    const int ii = c0 & 15;     // offset within group
#pragma unroll
    for (int r = 0; r < 16; ++r) {
        int t = t0 + rg * 16 + r;
        float* base = (t < 256) ? g_gx_lo : g_gx_hi;
        float4 o = make_float4(a[r][0].x + bx0.x, a[r][0].y + bx0.y,
                               a[r][1].x + bx1.x, a[r][1].y + bx1.y);
        *(float4*)(base + (((size_t)(t & 255) * 24 + j) * BB + b) * 16 + ii) = o;
    }
}

// ---------------------------------------------------------------------------
// Kernel B: GRU recurrence + FC. 128 blocks x 32 rows, 256 threads (8 warps).
// Warp w: all 32 rows x unit-triples [16w,16w+16). Lane (lh=l&15, uh=l>>4):
// rows {2lh, 2lh+1}, units [16w+8uh, +8). smem: w_h [128][384] (192KB) +
// double-buffered h[2][128 units][34] (34KB). One barrier per step.
// Per warp per k: 1 LDS.64 phase (h) + 6 LDS.128 phases (w) = 7 phases;
// 24 ffma2/thread/k -> FMA-bound at 96 cyc/k/SM.
// ---------------------------------------------------------------------------
#define HSTR 34
#define HBUF (HID * HSTR)

__global__ void __launch_bounds__(256, 1)
gru_kernel(const float* __restrict__ w_h,
           const float* __restrict__ b_h,
           const float* __restrict__ fc_w,
           const float* __restrict__ fc_b,
           float* __restrict__ out) {
    extern __shared__ float sm[];
    float* sWh = sm;              // [128][384]: sWh[k*384 + g*128 + u]
    float* sH  = sm + HID * C3;   // [2][128 units][HSTR]: sH[buf][u*HSTR + row]

    const int tid = threadIdx.x;
    const int w   = tid >> 5;
    const int l   = tid & 31;
    const int lh  = l & 15;       // row pair: rows 2lh, 2lh+1
    const int uh  = l >> 4;       // unit octet select
    const int u0  = 16 * w + 8 * uh;  // this thread's 8 units
    const int r0  = 2 * lh;
    const int row0 = blockIdx.x * 32;

    for (int idx = tid; idx < HID * C3; idx += 256) {
        int k = idx / C3, c = idx % C3;
        sWh[idx] = w_h[(size_t)(c >> 7) * HID * HID + k * HID + (c & 127)];
    }
    for (int idx = tid; idx < 2 * HBUF; idx += 256) sH[idx] = 0.0f;

    // biases for this thread's 8 units, per gate, as float2 pairs
    float2 bh[3][4];
#pragma unroll
    for (int g = 0; g < 3; ++g)
#pragma unroll
        for (int p = 0; p < 4; ++p)
            bh[g][p] = *(const float2*)(b_h + g * HID + u0 + 2 * p);

    float hold[2][8];
#pragma unroll
    for (int r = 0; r < 2; ++r)
#pragma unroll
        for (int jj = 0; jj < 8; ++jj) hold[r][jj] = 0.0f;

    __syncthreads();

    // gx prefetch: pg[g][rho][part] covers units u0+4*part.., row row0+r0+rho
    // gmem index: ((t*24 + 8g + w)*BB + row)*16 + 8*uh + 4*part
    float4 pg[3][2][2];
#pragma unroll
    for (int g = 0; g < 3; ++g)
#pragma unroll
        for (int rr = 0; rr < 2; ++rr)
#pragma unroll
            for (int pt = 0; pt < 2; ++pt)
                pg[g][rr][pt] = __ldg((const float4*)(
                    g_gx_lo + (((size_t)0 * 24 + 8 * g + w) * BB + row0 + r0 + rr) * 16
                            + 8 * uh + 4 * pt));

    for (int t = 0; t < TT; ++t) {
        const float* sHr = sH + (t & 1) * HBUF;
        float*       sHw = sH + ((t + 1) & 1) * HBUF;

        // init accumulators: r,z get gx + bias; n gets bias only (gx_n saved)
        float2 acc[2][3][4];
        float  gxn[2][8];
#pragma unroll
        for (int rr = 0; rr < 2; ++rr) {
#pragma unroll
            for (int pt = 0; pt < 2; ++pt) {
                float4 gr = pg[0][rr][pt];
                float4 gz = pg[1][rr][pt];
                float4 gn = pg[2][rr][pt];
                acc[rr][0][2*pt]   = make_float2(gr.x + bh[0][2*pt].x,   gr.y + bh[0][2*pt].y);
                acc[rr][0][2*pt+1] = make_float2(gr.z + bh[0][2*pt+1].x, gr.w + bh[0][2*pt+1].y);
                acc[rr][1][2*pt]   = make_float2(gz.x + bh[1][2*pt].x,   gz.y + bh[1][2*pt].y);
                acc[rr][1][2*pt+1] = make_float2(gz.z + bh[1][2*pt+1].x, gz.w + bh[1][2*pt+1].y);
                acc[rr][2][2*pt]   = bh[2][2*pt];
                acc[rr][2][2*pt+1] = bh[2][2*pt+1];
                gxn[rr][4*pt]   = gn.x; gxn[rr][4*pt+1] = gn.y;
                gxn[rr][4*pt+2] = gn.z; gxn[rr][4*pt+3] = gn.w;
            }
        }

        // prefetch gx for t+1 (hides under the k-loop)
        if (t + 1 < TT) {
            int t2 = t + 1;
            const float* base = (t2 < 256) ? g_gx_lo : g_gx_hi;
#pragma unroll
            for (int g = 0; g < 3; ++g)
#pragma unroll
                for (int rr = 0; rr < 2; ++rr)
#pragma unroll
                    for (int pt = 0; pt < 2; ++pt)
                        pg[g][rr][pt] = __ldg((const float4*)(
                            base + (((size_t)(t2 & 255) * 24 + 8 * g + w) * BB
                                    + row0 + r0 + rr) * 16 + 8 * uh + 4 * pt));
        }

        // matvec: acc[rho][g][p] += h[k][rho] * w_h[g][k][u0+2p..]
#pragma unroll 4
        for (int k = 0; k < HID; ++k) {
            float2 hv = *(const float2*)(sHr + k * HSTR + r0);   // rows r0, r0+1
            const float* wr = sWh + k * C3 + u0;
            float4 w0a = *(const float4*)(wr);
            float4 w0b = *(const float4*)(wr + 4);
            float4 w1a = *(const float4*)(wr + HID);
            float4 w1b = *(const float4*)(wr + HID + 4);
            float4 w2a = *(const float4*)(wr + 2 * HID);
            float4 w2b = *(const float4*)(wr + 2 * HID + 4);
            float2 wv[3][4];
            wv[0][0] = make_float2(w0a.x, w0a.y); wv[0][1] = make_float2(w0a.z, w0a.w);
            wv[0][2] = make_float2(w0b.x, w0b.y); wv[0][3] = make_float2(w0b.z, w0b.w);
            wv[1][0] = make_float2(w1a.x, w1a.y); wv[1][1] = make_float2(w1a.z, w1a.w);
            wv[1][2] = make_float2(w1b.x, w1b.y); wv[1][3] = make_float2(w1b.z, w1b.w);
            wv[2][0] = make_float2(w2a.x, w2a.y); wv[2][1] = make_float2(w2a.z, w2a.w);
            wv[2][2] = make_float2(w2b.x, w2b.y); wv[2][3] = make_float2(w2b.z, w2b.w);
            float hs[2] = {hv.x, hv.y};
#pragma unroll
            for (int rr = 0; rr < 2; ++rr) {
                float2 hh = make_float2(hs[rr], hs[rr]);
#pragma unroll
                for (int g = 0; g < 3; ++g) {
#pragma unroll
                    for (int p = 0; p < 4; ++p)
                        acc[rr][g][p] = ffma2(hh, wv[g][p], acc[rr][g][p]);
                }
            }
        }

        // gates + state update (all thread-local)
        float hn[2][8];
#pragma unroll
        for (int rr = 0; rr < 2; ++rr) {
#pragma unroll
            for (int p = 0; p < 4; ++p) {
#pragma unroll
                for (int q = 0; q < 2; ++q) {
                    int jj = 2 * p + q;
                    float ar = (q == 0) ? acc[rr][0][p].x : acc[rr][0][p].y;
                    float az = (q == 0) ? acc[rr][1][p].x : acc[rr][1][p].y;
                    float an = (q == 0) ? acc[rr][2][p].x : acc[rr][2][p].y;
                    float rg = sig1(ar);
                    float zg = sig1(az);
                    float ng = tanh1(gxn[rr][jj] + rg * an);
                    hn[rr][jj] = ng + zg * (hold[rr][jj] - ng);
                }
            }
        }

        // publish h(t+1) to the other buffer; one barrier per step
#pragma unroll
        for (int jj = 0; jj < 8; ++jj) {
            float2 hv = make_float2(hn[0][jj], hn[1][jj]);
            *(float2*)(sHw + (u0 + jj) * HSTR + r0) = hv;
        }
#pragma unroll
        for (int rr = 0; rr < 2; ++rr)
#pragma unroll
            for (int jj = 0; jj < 8; ++jj) hold[rr][jj] = hn[rr][jj];
        __syncthreads();
    }

    // FC epilogue: final h is in buffer (TT & 1) == 0
    const float* sHf = sH;   // TT=512 even -> buffer 0
    float* sFW = sWh;        // reuse w_h space (dead now)
    for (int idx = tid; idx < HID * 10; idx += 256) sFW[idx] = fc_w[idx];
    __syncthreads();
    for (int idx = tid; idx < 32 * 10; idx += 256) {
        int lr = idx / 10, col = idx % 10;
        float s = fc_b[col];
#pragma unroll 8
        for (int u = 0; u < HID; ++u)
            s += sHf[u * HSTR + lr] * sFW[u * 10 + col];
        out[(size_t)(row0 + lr) * 10 + col] = s;
    }
}

extern "C" void kernel_launch(void* const* d_in, const int* in_sizes, int n_in,
                              void* d_out, int out_size) {
    const float* x    = (const float*)d_in[0];
    const float* w_x  = (const float*)d_in[1];
    const float* b_x  = (const float*)d_in[2];
    const float* w_h  = (const float*)d_in[3];
    const float* b_h  = (const float*)d_in[4];
    const float* fc_w = (const float*)d_in[5];
    const float* fc_b = (const float*)d_in[6];
    float* out = (float*)d_out;

    const int smemA = (64 * INP + INP * C3) * sizeof(float);            // 50176 B
    const int smemB = (HID * C3 + 2 * HBUF) * sizeof(float);            // 231424 B
    cudaFuncSetAttribute(gx_kernel,  cudaFuncAttributeMaxDynamicSharedMemorySize, smemA);
    cudaFuncSetAttribute(gru_kernel, cudaFuncAttributeMaxDynamicSharedMemorySize, smemB);

    dim3 gA(BB, TT / 64);
    gx_kernel<<<gA, 384, smemA>>>(x, w_x, b_x);
    gru_kernel<<<128, 256, smemB>>>(w_h, b_h, fc_w, fc_b, out);
}

// round 4
// speedup vs baseline: 1.0463x; 1.0463x over previous
#include <cuda_runtime.h>
#include <cstdint>
#include <cstddef>

#define HID 128
#define C3  384
#define TT  512
#define BB  4096
#define INP 28

// 3.2 GB scratch for precomputed input projections, layout gx[t][b][c]
// (c = g*128 + u, 384 contiguous). Split in two halves by t (each 1.6 GB).
__device__ __align__(16) float g_gx_lo[(size_t)256 * BB * C3];
__device__ __align__(16) float g_gx_hi[(size_t)256 * BB * C3];

// Packed dual-fp32 FMA (Blackwell f32x2: 2 MACs per 2-cyc FMA slot).
static __device__ __forceinline__ float2 ffma2(float2 a, float2 b, float2 c) {
    unsigned long long ua, ub, uc, ud;
    ua = *reinterpret_cast<unsigned long long*>(&a);
    ub = *reinterpret_cast<unsigned long long*>(&b);
    uc = *reinterpret_cast<unsigned long long*>(&c);
    asm("fma.rn.f32x2 %0, %1, %2, %3;" : "=l"(ud) : "l"(ua), "l"(ub), "l"(uc));
    return *reinterpret_cast<float2*>(&ud);
}

static __device__ __forceinline__ float sig1(float x) {
    float e = __expf(-x);
    return __fdividef(1.0f, 1.0f + e);
}
static __device__ __forceinline__ float tanh1(float x) {
    float e = __expf(2.0f * x);
    return 1.0f - __fdividef(2.0f, e + 1.0f);
}

// ---------------------------------------------------------------------------
// Kernel A: gx[t][b][c] = sum_k x[b][t][k] * w_x[c/128][k][c%128] + b_x[c]
// One block per batch row b (4096 blocks, 384 threads). w_x loaded into smem
// ONCE, then 8 chunks of 64 timesteps. Thread: 16 t x 4 cols per chunk.
// ---------------------------------------------------------------------------
__global__ void __launch_bounds__(384)
gx_kernel(const float* __restrict__ x,
          const float* __restrict__ w_x,
          const float* __restrict__ b_x) {
    extern __shared__ float sm[];
    float* sWx = sm;            // [28][384] sWx[k][c]
    float* sXt = sm + INP * C3; // [28][64]  transposed x chunk

    const int b   = blockIdx.x;
    const int tid = threadIdx.x;

    for (int idx = tid; idx < INP * C3; idx += 384) {
        int k = idx / C3, c = idx % C3;
        sWx[idx] = w_x[(size_t)(c >> 7) * INP * HID + k * HID + (c & 127)];
    }

    const int cg = tid % 96;   // cols 4cg .. 4cg+3
    const int rg = tid / 96;   // timesteps rg*16 .. rg*16+15 within chunk
    const int c0 = 4 * cg;

    float2 bx0 = *(const float2*)(b_x + c0);
    float2 bx1 = *(const float2*)(b_x + c0 + 2);

    for (int tc = 0; tc < 8; ++tc) {
        const int t0 = 64 * tc;
        __syncthreads();   // sXt free for overwrite (also covers sWx on tc=0)
        const float* xg = x + ((size_t)b * TT + t0) * INP;
        for (int idx = tid; idx < 64 * INP; idx += 384) {
            int tt = idx / INP, k = idx % INP;
            sXt[k * 64 + tt] = xg[idx];
        }
        __syncthreads();

        float2 a[16][2];
#pragma unroll
        for (int r = 0; r < 16; ++r) {
            a[r][0] = make_float2(0.f, 0.f);
            a[r][1] = make_float2(0.f, 0.f);
        }

        const float* xp0 = sXt + rg * 16;
        const float* wp0 = sWx + c0;

#pragma unroll 4
        for (int k = 0; k < INP; ++k) {
            float4 wv = *(const float4*)(wp0 + k * C3);
            float2 w0 = make_float2(wv.x, wv.y);
            float2 w1 = make_float2(wv.z, wv.w);
            const float* xp = xp0 + k * 64;
            float4 xa = *(const float4*)(xp);
            float4 xb = *(const float4*)(xp + 4);
            float4 xc = *(const float4*)(xp + 8);
            float4 xd = *(const float4*)(xp + 12);
            float xs[16] = {xa.x, xa.y, xa.z, xa.w, xb.x, xb.y, xb.z, xb.w,
                            xc.x, xc.y, xc.z, xc.w, xd.x, xd.y, xd.z, xd.w};
#pragma unroll
            for (int r = 0; r < 16; ++r) {
                float2 xx = make_float2(xs[r], xs[r]);
                a[r][0] = ffma2(xx, w0, a[r][0]);
                a[r][1] = ffma2(xx, w1, a[r][1]);
            }
        }

#pragma unroll
        for (int r = 0; r < 16; ++r) {
            int t = t0 + rg * 16 + r;
            float* base = (t < 256) ? g_gx_lo : g_gx_hi;
            float4 o = make_float4(a[r][0].x + bx0.x, a[r][0].y + bx0.y,
                                   a[r][1].x + bx1.x, a[r][1].y + bx1.y);
            *(float4*)(base + ((size_t)(t & 255) * BB + b) * C3 + c0) = o;
        }
    }
}

// ---------------------------------------------------------------------------
// Kernel B: GRU recurrence + FC. 128 blocks x 32 rows, 512 threads (16 warps,
// 4 per SMSP). Warp W: rows 4*(W>>1)..+3, units 64*(W&1)..+63. Lane: 2 units.
// smem: w_h [128][384] (192KB) + h [128 units][36] (18KB). Lane-distinct
// weight loads (3x LDS.64 = 6 wf) + 1 broadcast LDS.128 (h) = 7 wf/warp/k.
// FMA floor: 4 warps/SMSP x 12 ffma2 x 2cyc = 96 cyc/k; crossbar 112/k.
// ---------------------------------------------------------------------------
__global__ void __launch_bounds__(512, 1)
gru_kernel(const float* __restrict__ w_h,
           const float* __restrict__ b_h,
           const float* __restrict__ fc_w,
           const float* __restrict__ fc_b,
           float* __restrict__ out) {
    extern __shared__ float sm[];
    float* sWh = sm;              // [128][384]: sWh[k*384 + g*128 + u]
    float* sH  = sm + HID * C3;   // [128 units][36]: sH[u*36 + row]

    const int tid = threadIdx.x;
    const int W   = tid >> 5;
    const int ug  = tid & 31;
    const int rg  = W >> 1;           // row group 0..7
    const int uh  = W & 1;            // unit half
    const int r0  = 4 * rg;           // 4 rows
    const int u0  = 64 * uh + 2 * ug; // 2 units
    const int row0 = blockIdx.x * 32;

    for (int idx = tid; idx < HID * C3; idx += 512) {
        int k = idx / C3, c = idx % C3;
        sWh[idx] = w_h[(size_t)(c >> 7) * HID * HID + k * HID + (c & 127)];
    }
    for (int idx = tid; idx < HID * 36; idx += 512) sH[idx] = 0.0f;

    float2 bh[3];
#pragma unroll
    for (int g = 0; g < 3; ++g)
        bh[g] = *(const float2*)(b_h + g * HID + u0);

    float hold[4][2];
#pragma unroll
    for (int r = 0; r < 4; ++r) { hold[r][0] = 0.0f; hold[r][1] = 0.0f; }

    __syncthreads();

    // gx prefetch for t=0: pg[g][r] = 2 floats (units u0,u0+1), row row0+r0+r
    float2 pg[3][4];
#pragma unroll
    for (int g = 0; g < 3; ++g)
#pragma unroll
        for (int r = 0; r < 4; ++r)
            pg[g][r] = __ldg((const float2*)(
                g_gx_lo + ((size_t)0 * BB + row0 + r0 + r) * C3 + g * HID + u0));

    for (int t = 0; t < TT; ++t) {
        // init accumulators; stash gx_n before prefetch clobbers pg
        float2 acc[4][3];
        float2 gxn[4];
#pragma unroll
        for (int r = 0; r < 4; ++r) {
            acc[r][0] = make_float2(pg[0][r].x + bh[0].x, pg[0][r].y + bh[0].y);
            acc[r][1] = make_float2(pg[1][r].x + bh[1].x, pg[1][r].y + bh[1].y);
            acc[r][2] = bh[2];
            gxn[r]    = pg[2][r];
        }

        if (t + 1 < TT) {
            int t2 = t + 1;
            const float* base = (t2 < 256) ? g_gx_lo : g_gx_hi;
#pragma unroll
            for (int g = 0; g < 3; ++g)
#pragma unroll
                for (int r = 0; r < 4; ++r)
                    pg[g][r] = __ldg((const float2*)(
                        base + ((size_t)(t2 & 255) * BB + row0 + r0 + r) * C3
                             + g * HID + u0));
        }

        // matvec over k: 1 bcast LDS.128 (h rows) + 3 LDS.64 (w), 12 ffma2
#pragma unroll 8
        for (int k = 0; k < HID; ++k) {
            float4 hk = *(const float4*)(sH + k * 36 + r0);
            const float* wr = sWh + k * C3 + u0;
            float2 w0 = *(const float2*)(wr);
            float2 w1 = *(const float2*)(wr + HID);
            float2 w2 = *(const float2*)(wr + 2 * HID);
            float hs[4] = {hk.x, hk.y, hk.z, hk.w};
#pragma unroll
            for (int r = 0; r < 4; ++r) {
                float2 hh = make_float2(hs[r], hs[r]);
                acc[r][0] = ffma2(hh, w0, acc[r][0]);
                acc[r][1] = ffma2(hh, w1, acc[r][1]);
                acc[r][2] = ffma2(hh, w2, acc[r][2]);
            }
        }

        // gates + state update (thread-local)
        float hn[4][2];
#pragma unroll
        for (int r = 0; r < 4; ++r) {
#pragma unroll
            for (int q = 0; q < 2; ++q) {
                float ar = (q == 0) ? acc[r][0].x : acc[r][0].y;
                float az = (q == 0) ? acc[r][1].x : acc[r][1].y;
                float an = (q == 0) ? acc[r][2].x : acc[r][2].y;
                float gx = (q == 0) ? gxn[r].x : gxn[r].y;
                float rr = sig1(ar);
                float zz = sig1(az);
                float nn = tanh1(gx + rr * an);
                hn[r][q] = nn + zz * (hold[r][q] - nn);
            }
        }

        __syncthreads();   // all reads of h(t) done
#pragma unroll
        for (int q = 0; q < 2; ++q) {
            float4 hv = make_float4(hn[0][q], hn[1][q], hn[2][q], hn[3][q]);
            *(float4*)(sH + (u0 + q) * 36 + r0) = hv;
        }
#pragma unroll
        for (int r = 0; r < 4; ++r) {
            hold[r][0] = hn[r][0];
            hold[r][1] = hn[r][1];
        }
        __syncthreads();   // h(t+1) visible
    }

    // FC epilogue
    float* sFW = sWh;   // reuse (w_h dead)
    for (int idx = tid; idx < HID * 10; idx += 512) sFW[idx] = fc_w[idx];
    __syncthreads();
    for (int idx = tid; idx < 32 * 10; idx += 512) {
        int lr = idx / 10, col = idx % 10;
        float s = fc_b[col];
#pragma unroll 8
        for (int u = 0; u < HID; ++u)
            s += sH[u * 36 + lr] * sFW[u * 10 + col];
        out[(size_t)(row0 + lr) * 10 + col] = s;
    }
}

extern "C" void kernel_launch(void* const* d_in, const int* in_sizes, int n_in,
                              void* d_out, int out_size) {
    const float* x    = (const float*)d_in[0];
    const float* w_x  = (const float*)d_in[1];
    const float* b_x  = (const float*)d_in[2];
    const float* w_h  = (const float*)d_in[3];
    const float* b_h  = (const float*)d_in[4];
    const float* fc_w = (const float*)d_in[5];
    const float* fc_b = (const float*)d_in[6];
    float* out = (float*)d_out;

    const int smemA = (INP * C3 + 64 * INP) * sizeof(float);   // 50176 B
    const int smemB = (HID * C3 + HID * 36) * sizeof(float);   // 215040 B
    cudaFuncSetAttribute(gx_kernel,  cudaFuncAttributeMaxDynamicSharedMemorySize, smemA);
    cudaFuncSetAttribute(gru_kernel, cudaFuncAttributeMaxDynamicSharedMemorySize, smemB);

    gx_kernel<<<BB, 384, smemA>>>(x, w_x, b_x);
    gru_kernel<<<128, 512, smemB>>>(w_h, b_h, fc_w, fc_b, out);
}

// round 5
// speedup vs baseline: 1.0833x; 1.0354x over previous
#include <cuda_runtime.h>
#include <cstdint>
#include <cstddef>

#define HID 128
#define C3  384
#define TT  512
#define BB  4096
#define INP 28

// 3.2 GB scratch for precomputed input projections, layout gx[t][b][c]
// (c = g*128 + u). Split in two halves by t (each 1.6 GB).
__device__ __align__(16) float g_gx_lo[(size_t)256 * BB * C3];
__device__ __align__(16) float g_gx_hi[(size_t)256 * BB * C3];

// Packed dual-fp32 FMA (Blackwell f32x2: 2 MACs per 2-cyc FMA slot).
static __device__ __forceinline__ float2 ffma2(float2 a, float2 b, float2 c) {
    unsigned long long ua, ub, uc, ud;
    ua = *reinterpret_cast<unsigned long long*>(&a);
    ub = *reinterpret_cast<unsigned long long*>(&b);
    uc = *reinterpret_cast<unsigned long long*>(&c);
    asm("fma.rn.f32x2 %0, %1, %2, %3;" : "=l"(ud) : "l"(ua), "l"(ub), "l"(uc));
    return *reinterpret_cast<float2*>(&ud);
}

static __device__ __forceinline__ float sig1(float x) {
    float e = __expf(-x);
    return __fdividef(1.0f, 1.0f + e);
}
static __device__ __forceinline__ float tanh1(float x) {
    float e = __expf(2.0f * x);
    return 1.0f - __fdividef(2.0f, e + 1.0f);
}

// ---------------------------------------------------------------------------
// Kernel A: gx[t][b][c] = sum_k x[b][t][k] * w_x[c/128][k][c%128] + b_x[c]
// One block per batch row b (4096 blocks, 384 threads). w_x in smem once,
// 8 chunks of 64 timesteps. Thread: 16 t x 4 cols; accumulators paired over
// TIMESTEPS so x pairs come free from float4 loads (only 4 w-splats per k).
// ---------------------------------------------------------------------------
__global__ void __launch_bounds__(384)
gx_kernel(const float* __restrict__ x,
          const float* __restrict__ w_x,
          const float* __restrict__ b_x) {
    extern __shared__ float sm[];
    float* sWx = sm;            // [28][384]
    float* sXt = sm + INP * C3; // [28][64] transposed x chunk

    const int b   = blockIdx.x;
    const int tid = threadIdx.x;

    for (int idx = tid; idx < INP * C3; idx += 384) {
        int k = idx / C3, c = idx % C3;
        sWx[idx] = w_x[(size_t)(c >> 7) * INP * HID + k * HID + (c & 127)];
    }

    const int cg = tid % 96;
    const int rg = tid / 96;
    const int c0 = 4 * cg;

    float2 bx0 = *(const float2*)(b_x + c0);
    float2 bx1 = *(const float2*)(b_x + c0 + 2);
    float bxs[4] = {bx0.x, bx0.y, bx1.x, bx1.y};

    for (int tc = 0; tc < 8; ++tc) {
        const int t0 = 64 * tc;
        __syncthreads();
        const float* xg = x + ((size_t)b * TT + t0) * INP;
        for (int idx = tid; idx < 64 * INP; idx += 384) {
            int tt = idx / INP, k = idx % INP;
            sXt[k * 64 + tt] = xg[idx];
        }
        __syncthreads();

        // acc[p][c] : p = timestep pair (8), c = col (4); .x = even t, .y = odd
        float2 a[8][4];
#pragma unroll
        for (int p = 0; p < 8; ++p)
#pragma unroll
            for (int c = 0; c < 4; ++c) a[p][c] = make_float2(0.f, 0.f);

        const float* xp0 = sXt + rg * 16;
        const float* wp0 = sWx + c0;

#pragma unroll 4
        for (int k = 0; k < INP; ++k) {
            float4 wv = *(const float4*)(wp0 + k * C3);
            float2 wc[4];
            wc[0] = make_float2(wv.x, wv.x);
            wc[1] = make_float2(wv.y, wv.y);
            wc[2] = make_float2(wv.z, wv.w == wv.w ? wv.z : wv.z);  // splat z
            wc[3] = make_float2(wv.w, wv.w);
            const float* xp = xp0 + k * 64;
            float4 xa = *(const float4*)(xp);
            float4 xb = *(const float4*)(xp + 4);
            float4 xc = *(const float4*)(xp + 8);
            float4 xd = *(const float4*)(xp + 12);
            float2 hp[8];
            hp[0] = make_float2(xa.x, xa.y); hp[1] = make_float2(xa.z, xa.w);
            hp[2] = make_float2(xb.x, xb.y); hp[3] = make_float2(xb.z, xb.w);
            hp[4] = make_float2(xc.x, xc.y); hp[5] = make_float2(xc.z, xc.w);
            hp[6] = make_float2(xd.x, xd.y); hp[7] = make_float2(xd.z, xd.w);
#pragma unroll
            for (int p = 0; p < 8; ++p) {
#pragma unroll
                for (int c = 0; c < 4; ++c)
                    a[p][c] = ffma2(hp[p], wc[c], a[p][c]);
            }
        }

#pragma unroll
        for (int r = 0; r < 16; ++r) {
            int p = r >> 1, q = r & 1;
            int t = t0 + rg * 16 + r;
            float* base = (t < 256) ? g_gx_lo : g_gx_hi;
            float v0 = (q ? a[p][0].y : a[p][0].x) + bxs[0];
            float v1 = (q ? a[p][1].y : a[p][1].x) + bxs[1];
            float v2 = (q ? a[p][2].y : a[p][2].x) + bxs[2];
            float v3 = (q ? a[p][3].y : a[p][3].x) + bxs[3];
            *(float4*)(base + ((size_t)(t & 255) * BB + b) * C3 + c0) =
                make_float4(v0, v1, v2, v3);
        }
    }
}

// ---------------------------------------------------------------------------
// Kernel B: GRU recurrence + FC. 128 blocks x 32 rows, 512 threads (16 warps).
// Warp W: row group rg=W&3 (rows 8rg..8rg+7), unit quarter cq=W>>2
// (units 32cq..32cq+31). Thread: 8 rows x 1 unit x 3 gates.
// Per warp per k: 2 uniform LDS.128 (h, broadcast) + 3 coalesced LDS.32 (w)
// = 5 wavefronts; weight bytes/SM/k = 6KB (4x redundancy, was 8x).
// FMA: 12 ffma2/thread/k -> 96 cyc/SMSP/k floor; LDS 80 -> FMA-bound.
// ---------------------------------------------------------------------------
#define HSTR 36

__global__ void __launch_bounds__(512, 1)
gru_kernel(const float* __restrict__ w_h,
           const float* __restrict__ b_h,
           const float* __restrict__ fc_w,
           const float* __restrict__ fc_b,
           float* __restrict__ out) {
    extern __shared__ float sm[];
    float* sWh = sm;              // [128][384]: sWh[k*384 + g*128 + u]
    float* sH  = sm + HID * C3;   // [128 units][HSTR]: sH[u*HSTR + row]

    const int tid = threadIdx.x;
    const int W   = tid >> 5;
    const int ln  = tid & 31;
    const int rg  = W & 3;            // row group
    const int cq  = W >> 2;           // unit quarter
    const int r0  = 8 * rg;           // 8 rows
    const int u   = 32 * cq + ln;     // 1 unit
    const int row0 = blockIdx.x * 32;

    for (int idx = tid; idx < HID * C3; idx += 512) {
        int k = idx / C3, c = idx % C3;
        sWh[idx] = w_h[(size_t)(c >> 7) * HID * HID + k * HID + (c & 127)];
    }
    for (int idx = tid; idx < HID * HSTR; idx += 512) sH[idx] = 0.0f;

    const float bhr = b_h[u];
    const float bhz = b_h[HID + u];
    const float bhn = b_h[2 * HID + u];

    float hold[8];
#pragma unroll
    for (int r = 0; r < 8; ++r) hold[r] = 0.0f;

    __syncthreads();

    // gx prefetch for t=0: pg[g][r], row row0+r0+r, col g*128+u (coalesced)
    float pg[3][8];
#pragma unroll
    for (int g = 0; g < 3; ++g)
#pragma unroll
        for (int r = 0; r < 8; ++r)
            pg[g][r] = __ldg(g_gx_lo + ((size_t)(row0 + r0 + r)) * C3 + g * HID + u);

    for (int t = 0; t < TT; ++t) {
        // acc[g][p]: gate g, row pair p (.x = row 2p, .y = row 2p+1)
        float2 acc[3][4];
        float  gxn[8];
#pragma unroll
        for (int p = 0; p < 4; ++p) {
            acc[0][p] = make_float2(pg[0][2*p] + bhr, pg[0][2*p+1] + bhr);
            acc[1][p] = make_float2(pg[1][2*p] + bhz, pg[1][2*p+1] + bhz);
            acc[2][p] = make_float2(bhn, bhn);
            gxn[2*p]   = pg[2][2*p];
            gxn[2*p+1] = pg[2][2*p+1];
        }

        if (t + 1 < TT) {
            int t2 = t + 1;
            const float* base = (t2 < 256) ? g_gx_lo : g_gx_hi;
            const float* gb = base + ((size_t)(t2 & 255) * BB + row0 + r0) * C3 + u;
#pragma unroll
            for (int g = 0; g < 3; ++g)
#pragma unroll
                for (int r = 0; r < 8; ++r)
                    pg[g][r] = __ldg(gb + (size_t)r * C3 + g * HID);
        }

        // matvec over k: h rows broadcast, weights lane-distinct scalars
#pragma unroll 8
        for (int k = 0; k < HID; ++k) {
            float4 ha = *(const float4*)(sH + k * HSTR + r0);
            float4 hb = *(const float4*)(sH + k * HSTR + r0 + 4);
            const float* wr = sWh + k * C3 + u;
            float w0 = wr[0];
            float w1 = wr[HID];
            float w2 = wr[2 * HID];
            float2 wv0 = make_float2(w0, w0);
            float2 wv1 = make_float2(w1, w1);
            float2 wv2 = make_float2(w2, w2);
            float2 hp[4];
            hp[0] = make_float2(ha.x, ha.y);
            hp[1] = make_float2(ha.z, ha.w);
            hp[2] = make_float2(hb.x, hb.y);
            hp[3] = make_float2(hb.z, hb.w);
#pragma unroll
            for (int p = 0; p < 4; ++p) {
                acc[0][p] = ffma2(hp[p], wv0, acc[0][p]);
                acc[1][p] = ffma2(hp[p], wv1, acc[1][p]);
                acc[2][p] = ffma2(hp[p], wv2, acc[2][p]);
            }
        }

        // gates + state update (thread-local: 8 rows x unit u)
        float hn[8];
#pragma unroll
        for (int p = 0; p < 4; ++p) {
#pragma unroll
            for (int q = 0; q < 2; ++q) {
                int r = 2 * p + q;
                float ar = q ? acc[0][p].y : acc[0][p].x;
                float az = q ? acc[1][p].y : acc[1][p].x;
                float an = q ? acc[2][p].y : acc[2][p].x;
                float rr = sig1(ar);
                float zz = sig1(az);
                float nn = tanh1(gxn[r] + rr * an);
                hn[r] = nn + zz * (hold[r] - nn);
            }
        }

        __syncthreads();   // all reads of h(t) done
        *(float4*)(sH + u * HSTR + r0)     = make_float4(hn[0], hn[1], hn[2], hn[3]);
        *(float4*)(sH + u * HSTR + r0 + 4) = make_float4(hn[4], hn[5], hn[6], hn[7]);
#pragma unroll
        for (int r = 0; r < 8; ++r) hold[r] = hn[r];
        __syncthreads();   // h(t+1) visible
    }

    // FC epilogue
    float* sFW = sWh;   // reuse (w_h dead)
    for (int idx = tid; idx < HID * 10; idx += 512) sFW[idx] = fc_w[idx];
    __syncthreads();
    for (int idx = tid; idx < 32 * 10; idx += 512) {
        int lr = idx / 10, col = idx % 10;
        float s = fc_b[col];
#pragma unroll 8
        for (int uu = 0; uu < HID; ++uu)
            s += sH[uu * HSTR + lr] * sFW[uu * 10 + col];
        out[(size_t)(row0 + lr) * 10 + col] = s;
    }
}

extern "C" void kernel_launch(void* const* d_in, const int* in_sizes, int n_in,
                              void* d_out, int out_size) {
    const float* x    = (const float*)d_in[0];
    const float* w_x  = (const float*)d_in[1];
    const float* b_x  = (const float*)d_in[2];
    const float* w_h  = (const float*)d_in[3];
    const float* b_h  = (const float*)d_in[4];
    const float* fc_w = (const float*)d_in[5];
    const float* fc_b = (const float*)d_in[6];
    float* out = (float*)d_out;

    const int smemA = (INP * C3 + 64 * INP) * sizeof(float);    // 50176 B
    const int smemB = (HID * C3 + HID * HSTR) * sizeof(float);  // 215040 B
    cudaFuncSetAttribute(gx_kernel,  cudaFuncAttributeMaxDynamicSharedMemorySize, smemA);
    cudaFuncSetAttribute(gru_kernel, cudaFuncAttributeMaxDynamicSharedMemorySize, smemB);

    gx_kernel<<<BB, 384, smemA>>>(x, w_x, b_x);
    gru_kernel<<<128, 512, smemB>>>(w_h, b_h, fc_w, fc_b, out);
}

// round 7
// speedup vs baseline: 1.1656x; 1.0760x over previous
#include <cuda_runtime.h>
#include <cstdint>
#include <cstddef>

#define HID 128
#define C3  384
#define TT  512
#define BB  4096
#define INP 28

// 3.2 GB scratch for precomputed input projections, layout gx[t][b][c]
// (c = g*128 + u). Split in two halves by t (each 1.6 GB).
__device__ __align__(16) float g_gx_lo[(size_t)256 * BB * C3];
__device__ __align__(16) float g_gx_hi[(size_t)256 * BB * C3];

// Packed dual-fp32 FMA (Blackwell f32x2: 2 MACs per 2-cyc FMA slot).
static __device__ __forceinline__ float2 ffma2(float2 a, float2 b, float2 c) {
    unsigned long long ua, ub, uc, ud;
    ua = *reinterpret_cast<unsigned long long*>(&a);
    ub = *reinterpret_cast<unsigned long long*>(&b);
    uc = *reinterpret_cast<unsigned long long*>(&c);
    asm("fma.rn.f32x2 %0, %1, %2, %3;" : "=l"(ud) : "l"(ua), "l"(ub), "l"(uc));
    return *reinterpret_cast<float2*>(&ud);
}

static __device__ __forceinline__ float sig1(float x) {
    float e = __expf(-x);
    return __fdividef(1.0f, 1.0f + e);
}
static __device__ __forceinline__ float tanh1(float x) {
    float e = __expf(2.0f * x);
    return 1.0f - __fdividef(2.0f, e + 1.0f);
}

// ---------------------------------------------------------------------------
// Kernel A: gx[t][b][c] = sum_k x[b][t][k] * w_x[c/128][k][c%128] + b_x[c]
// One block per batch row b (4096 blocks, 384 threads), w_x in smem once,
// 16 chunks of 32 timesteps. Thread: 8 t x 4 cols (32 accum floats) so regs
// stay under ~85 -> __launch_bounds__(384,2): 2 blocks/SM, 6 warps/SMSP.
// ---------------------------------------------------------------------------
__global__ void __launch_bounds__(384, 2)
gx_kernel(const float* __restrict__ x,
          const float* __restrict__ w_x,
          const float* __restrict__ b_x) {
    extern __shared__ float sm[];
    float* sWx = sm;            // [28][384]
    float* sXt = sm + INP * C3; // [28][32] transposed x chunk

    const int b   = blockIdx.x;
    const int tid = threadIdx.x;

    for (int idx = tid; idx < INP * C3; idx += 384) {
        int k = idx / C3, c = idx % C3;
        sWx[idx] = w_x[(size_t)(c >> 7) * INP * HID + k * HID + (c & 127)];
    }

    const int cg = tid % 96;   // cols 4cg..4cg+3
    const int rg = tid / 96;   // timesteps rg*8..rg*8+7 within chunk
    const int c0 = 4 * cg;

    float2 bx0 = *(const float2*)(b_x + c0);
    float2 bx1 = *(const float2*)(b_x + c0 + 2);
    float bxs[4] = {bx0.x, bx0.y, bx1.x, bx1.y};

    for (int tc = 0; tc < 16; ++tc) {
        const int t0 = 32 * tc;
        __syncthreads();   // sXt free (covers sWx fill on tc=0)
        const float* xg = x + ((size_t)b * TT + t0) * INP;
        for (int idx = tid; idx < 32 * INP; idx += 384) {
            int tt = idx / INP, k = idx % INP;
            sXt[k * 32 + tt] = xg[idx];
        }
        __syncthreads();

        // a[p][c]: p = timestep pair (4), c = col (4); .x even t, .y odd t
        float2 a[4][4];
#pragma unroll
        for (int p = 0; p < 4; ++p)
#pragma unroll
            for (int c = 0; c < 4; ++c) a[p][c] = make_float2(0.f, 0.f);

        const float* xp0 = sXt + rg * 8;
        const float* wp0 = sWx + c0;

#pragma unroll 7
        for (int k = 0; k < INP; ++k) {
            float4 wv = *(const float4*)(wp0 + k * C3);
            float2 wc[4];
            wc[0] = make_float2(wv.x, wv.x);
            wc[1] = make_float2(wv.y, wv.y);
            wc[2] = make_float2(wv.z, wv.z);
            wc[3] = make_float2(wv.w, wv.w);
            const float* xp = xp0 + k * 32;
            float4 xa = *(const float4*)(xp);
            float4 xb = *(const float4*)(xp + 4);
            float2 hp[4];
            hp[0] = make_float2(xa.x, xa.y); hp[1] = make_float2(xa.z, xa.w);
            hp[2] = make_float2(xb.x, xb.y); hp[3] = make_float2(xb.z, xb.w);
#pragma unroll
            for (int p = 0; p < 4; ++p) {
#pragma unroll
                for (int c = 0; c < 4; ++c)
                    a[p][c] = ffma2(hp[p], wc[c], a[p][c]);
            }
        }

#pragma unroll
        for (int r = 0; r < 8; ++r) {
            int p = r >> 1, q = r & 1;
            int t = t0 + rg * 8 + r;
            float* base = (t < 256) ? g_gx_lo : g_gx_hi;
            float v0 = (q ? a[p][0].y : a[p][0].x) + bxs[0];
            float v1 = (q ? a[p][1].y : a[p][1].x) + bxs[1];
            float v2 = (q ? a[p][2].y : a[p][2].x) + bxs[2];
            float v3 = (q ? a[p][3].y : a[p][3].x) + bxs[3];
            *(float4*)(base + ((size_t)(t & 255) * BB + b) * C3 + c0) =
                make_float4(v0, v1, v2, v3);
        }
    }
}

// ---------------------------------------------------------------------------
// Kernel B: GRU recurrence + FC. 128 blocks x 32 rows, 512 threads (16 warps).
// Warp W: rows 8*(W&3).., units 32*(W>>2)..; thread: 8 rows x 1 unit x 3 gates.
// Double-buffered h, INTERLEAVED layout sH[unit][buf][row]: unit stride 68
// floats (= 2*32 + 4 pad, multiple of 4 -> LDS.128 aligned for every k),
// buffer offset 32. ONE barrier per step. Total smem 231424 B (fits).
// Per warp per k: 2 uniform LDS.128 (h) + 3 coalesced LDS.32 (w) = 5 wf.
// ---------------------------------------------------------------------------
#define USTR 68   // unit stride in floats (multiple of 4: float4-aligned)

__global__ void __launch_bounds__(512, 1)
gru_kernel(const float* __restrict__ w_h,
           const float* __restrict__ b_h,
           const float* __restrict__ fc_w,
           const float* __restrict__ fc_b,
           float* __restrict__ out) {
    extern __shared__ float sm[];
    float* sWh = sm;              // [128][384]: sWh[k*384 + g*128 + u]
    float* sH  = sm + HID * C3;   // [128 units][2 bufs][32+ rows], stride USTR

    const int tid = threadIdx.x;
    const int W   = tid >> 5;
    const int ln  = tid & 31;
    const int rg  = W & 3;
    const int cq  = W >> 2;
    const int r0  = 8 * rg;
    const int u   = 32 * cq + ln;
    const int row0 = blockIdx.x * 32;

    for (int idx = tid; idx < HID * C3; idx += 512) {
        int k = idx / C3, c = idx % C3;
        sWh[idx] = w_h[(size_t)(c >> 7) * HID * HID + k * HID + (c & 127)];
    }
    for (int idx = tid; idx < HID * USTR; idx += 512) sH[idx] = 0.0f;

    const float bhr = b_h[u];
    const float bhz = b_h[HID + u];
    const float bhn = b_h[2 * HID + u];

    float hold[8];
#pragma unroll
    for (int r = 0; r < 8; ++r) hold[r] = 0.0f;

    __syncthreads();

    float pg[3][8];
#pragma unroll
    for (int g = 0; g < 3; ++g)
#pragma unroll
        for (int r = 0; r < 8; ++r)
            pg[g][r] = __ldg(g_gx_lo + ((size_t)(row0 + r0 + r)) * C3 + g * HID + u);

    for (int t = 0; t < TT; ++t) {
        const int bufR = (t & 1) * 32;         // read offset within unit
        const int bufW = ((t + 1) & 1) * 32;   // write offset

        float2 acc[3][4];
        float  gxn[8];
#pragma unroll
        for (int p = 0; p < 4; ++p) {
            acc[0][p] = make_float2(pg[0][2*p] + bhr, pg[0][2*p+1] + bhr);
            acc[1][p] = make_float2(pg[1][2*p] + bhz, pg[1][2*p+1] + bhz);
            acc[2][p] = make_float2(bhn, bhn);
            gxn[2*p]   = pg[2][2*p];
            gxn[2*p+1] = pg[2][2*p+1];
        }

        if (t + 1 < TT) {
            int t2 = t + 1;
            const float* base = (t2 < 256) ? g_gx_lo : g_gx_hi;
            const float* gb = base + ((size_t)(t2 & 255) * BB + row0 + r0) * C3 + u;
#pragma unroll
            for (int g = 0; g < 3; ++g)
#pragma unroll
                for (int r = 0; r < 8; ++r)
                    pg[g][r] = __ldg(gb + (size_t)r * C3 + g * HID);
        }

        // matvec: h rows uniform-broadcast (aligned float4), weights scalar
        const float* sHr = sH + bufR + r0;
#pragma unroll 8
        for (int k = 0; k < HID; ++k) {
            float4 ha = *(const float4*)(sHr + k * USTR);
            float4 hb = *(const float4*)(sHr + k * USTR + 4);
            const float* wr = sWh + k * C3 + u;
            float w0 = wr[0];
            float w1 = wr[HID];
            float w2 = wr[2 * HID];
            float2 wv0 = make_float2(w0, w0);
            float2 wv1 = make_float2(w1, w1);
            float2 wv2 = make_float2(w2, w2);
            float2 hp[4];
            hp[0] = make_float2(ha.x, ha.y);
            hp[1] = make_float2(ha.z, ha.w);
            hp[2] = make_float2(hb.x, hb.y);
            hp[3] = make_float2(hb.z, hb.w);
#pragma unroll
            for (int p = 0; p < 4; ++p) {
                acc[0][p] = ffma2(hp[p], wv0, acc[0][p]);
                acc[1][p] = ffma2(hp[p], wv1, acc[1][p]);
                acc[2][p] = ffma2(hp[p], wv2, acc[2][p]);
            }
        }

        float hn[8];
#pragma unroll
        for (int p = 0; p < 4; ++p) {
#pragma unroll
            for (int q = 0; q < 2; ++q) {
                int r = 2 * p + q;
                float ar = q ? acc[0][p].y : acc[0][p].x;
                float az = q ? acc[1][p].y : acc[1][p].x;
                float an = q ? acc[2][p].y : acc[2][p].x;
                float rr = sig1(ar);
                float zz = sig1(az);
                float nn = tanh1(gxn[r] + rr * an);
                hn[r] = nn + zz * (hold[r] - nn);
            }
        }

        // write h(t+1) into the other buffer slot of this unit
        float* hw = sH + u * USTR + bufW + r0;
        *(float4*)(hw)     = make_float4(hn[0], hn[1], hn[2], hn[3]);
        *(float4*)(hw + 4) = make_float4(hn[4], hn[5], hn[6], hn[7]);
#pragma unroll
        for (int r = 0; r < 8; ++r) hold[r] = hn[r];
        __syncthreads();   // single barrier per step
    }

    // FC epilogue: final h in buffer slot (TT & 1)==0 -> offset 0
    float* sFW = sWh;
    for (int idx = tid; idx < HID * 10; idx += 512) sFW[idx] = fc_w[idx];
    __syncthreads();
    for (int idx = tid; idx < 32 * 10; idx += 512) {
        int lr = idx / 10, col = idx % 10;
        float s = fc_b[col];
#pragma unroll 8
        for (int uu = 0; uu < HID; ++uu)
            s += sH[uu * USTR + lr] * sFW[uu * 10 + col];
        out[(size_t)(row0 + lr) * 10 + col] = s;
    }
}

extern "C" void kernel_launch(void* const* d_in, const int* in_sizes, int n_in,
                              void* d_out, int out_size) {
    const float* x    = (const float*)d_in[0];
    const float* w_x  = (const float*)d_in[1];
    const float* b_x  = (const float*)d_in[2];
    const float* w_h  = (const float*)d_in[3];
    const float* b_h  = (const float*)d_in[4];
    const float* fc_w = (const float*)d_in[5];
    const float* fc_b = (const float*)d_in[6];
    float* out = (float*)d_out;

    const int smemA = (INP * C3 + 32 * INP) * sizeof(float);      // 46592 B
    const int smemB = (HID * C3 + HID * USTR) * sizeof(float);    // 231424 B
    cudaFuncSetAttribute(gx_kernel,  cudaFuncAttributeMaxDynamicSharedMemorySize, smemA);
    cudaFuncSetAttribute(gru_kernel, cudaFuncAttributeMaxDynamicSharedMemorySize, smemB);

    gx_kernel<<<BB, 384, smemA>>>(x, w_x, b_x);
    gru_kernel<<<128, 512, smemB>>>(w_h, b_h, fc_w, fc_b, out);
}

// round 9
// speedup vs baseline: 2.1566x; 1.8502x over previous
#include <cuda_runtime.h>
#include <cuda_fp16.h>
#include <cstdint>
#include <cstddef>

#define HID 128
#define C3  384
#define TT  512
#define BB  4096
#define INP 28

// 3.2 GB scratch: gx[t][b][c], c = g*128+u. Split in halves by t.
__device__ __align__(16) float g_gx_lo[(size_t)256 * BB * C3];
__device__ __align__(16) float g_gx_hi[(size_t)256 * BB * C3];

// Packed dual-fp32 FMA
static __device__ __forceinline__ float2 ffma2(float2 a, float2 b, float2 c) {
    unsigned long long ua, ub, uc, ud;
    ua = *reinterpret_cast<unsigned long long*>(&a);
    ub = *reinterpret_cast<unsigned long long*>(&b);
    uc = *reinterpret_cast<unsigned long long*>(&c);
    asm("fma.rn.f32x2 %0, %1, %2, %3;" : "=l"(ud) : "l"(ua), "l"(ub), "l"(uc));
    return *reinterpret_cast<float2*>(&ud);
}
static __device__ __forceinline__ float sig1(float x) {
    float e = __expf(-x);
    return __fdividef(1.0f, 1.0f + e);
}
static __device__ __forceinline__ float tanh1(float x) {
    float e = __expf(2.0f * x);
    return 1.0f - __fdividef(2.0f, e + 1.0f);
}

static __device__ __forceinline__ uint32_t smem_u32(const void* p) {
    uint32_t a;
    asm("{ .reg .u64 t; cvta.to.shared.u64 t, %1; cvt.u32.u64 %0, t; }"
        : "=r"(a) : "l"(p));
    return a;
}
static __device__ __forceinline__ void ldsm4(uint32_t& r0, uint32_t& r1,
                                             uint32_t& r2, uint32_t& r3, uint32_t a) {
    asm volatile("ldmatrix.sync.aligned.m8n8.x4.shared.b16 {%0,%1,%2,%3}, [%4];"
                 : "=r"(r0), "=r"(r1), "=r"(r2), "=r"(r3) : "r"(a));
}
static __device__ __forceinline__ void ldsm4t(uint32_t& r0, uint32_t& r1,
                                              uint32_t& r2, uint32_t& r3, uint32_t a) {
    asm volatile("ldmatrix.sync.aligned.m8n8.x4.trans.shared.b16 {%0,%1,%2,%3}, [%4];"
                 : "=r"(r0), "=r"(r1), "=r"(r2), "=r"(r3) : "r"(a));
}
static __device__ __forceinline__ void mma16816(float* d,
        uint32_t a0, uint32_t a1, uint32_t a2, uint32_t a3,
        uint32_t b0, uint32_t b1) {
    asm volatile("mma.sync.aligned.m16n8k16.row.col.f32.f16.f16.f32 "
                 "{%0,%1,%2,%3},{%4,%5,%6,%7},{%8,%9},{%0,%1,%2,%3};"
                 : "+f"(d[0]), "+f"(d[1]), "+f"(d[2]), "+f"(d[3])
                 : "r"(a0), "r"(a1), "r"(a2), "r"(a3), "r"(b0), "r"(b1));
}

// ---------------------------------------------------------------------------
// Kernel A: unchanged from R7 (passing, 1.19 ms)
// ---------------------------------------------------------------------------
__global__ void __launch_bounds__(384, 2)
gx_kernel(const float* __restrict__ x,
          const float* __restrict__ w_x,
          const float* __restrict__ b_x) {
    extern __shared__ float sm[];
    float* sWx = sm;
    float* sXt = sm + INP * C3;

    const int b   = blockIdx.x;
    const int tid = threadIdx.x;

    for (int idx = tid; idx < INP * C3; idx += 384) {
        int k = idx / C3, c = idx % C3;
        sWx[idx] = w_x[(size_t)(c >> 7) * INP * HID + k * HID + (c & 127)];
    }

    const int cg = tid % 96;
    const int rg = tid / 96;
    const int c0 = 4 * cg;

    float2 bx0 = *(const float2*)(b_x + c0);
    float2 bx1 = *(const float2*)(b_x + c0 + 2);
    float bxs[4] = {bx0.x, bx0.y, bx1.x, bx1.y};

    for (int tc = 0; tc < 16; ++tc) {
        const int t0 = 32 * tc;
        __syncthreads();
        const float* xg = x + ((size_t)b * TT + t0) * INP;
        for (int idx = tid; idx < 32 * INP; idx += 384) {
            int tt = idx / INP, k = idx % INP;
            sXt[k * 32 + tt] = xg[idx];
        }
        __syncthreads();

        float2 a[4][4];
#pragma unroll
        for (int p = 0; p < 4; ++p)
#pragma unroll
            for (int c = 0; c < 4; ++c) a[p][c] = make_float2(0.f, 0.f);

        const float* xp0 = sXt + rg * 8;
        const float* wp0 = sWx + c0;

#pragma unroll 7
        for (int k = 0; k < INP; ++k) {
            float4 wv = *(const float4*)(wp0 + k * C3);
            float2 wc[4];
            wc[0] = make_float2(wv.x, wv.x);
            wc[1] = make_float2(wv.y, wv.y);
            wc[2] = make_float2(wv.z, wv.z);
            wc[3] = make_float2(wv.w, wv.w);
            const float* xp = xp0 + k * 32;
            float4 xa = *(const float4*)(xp);
            float4 xb = *(const float4*)(xp + 4);
            float2 hp[4];
            hp[0] = make_float2(xa.x, xa.y); hp[1] = make_float2(xa.z, xa.w);
            hp[2] = make_float2(xb.x, xb.y); hp[3] = make_float2(xb.z, xb.w);
#pragma unroll
            for (int p = 0; p < 4; ++p) {
#pragma unroll
                for (int c = 0; c < 4; ++c)
                    a[p][c] = ffma2(hp[p], wc[c], a[p][c]);
            }
        }

#pragma unroll
        for (int r = 0; r < 8; ++r) {
            int p = r >> 1, q = r & 1;
            int t = t0 + rg * 8 + r;
            float* base = (t < 256) ? g_gx_lo : g_gx_hi;
            float v0 = (q ? a[p][0].y : a[p][0].x) + bxs[0];
            float v1 = (q ? a[p][1].y : a[p][1].x) + bxs[1];
            float v2 = (q ? a[p][2].y : a[p][2].x) + bxs[2];
            float v3 = (q ? a[p][3].y : a[p][3].x) + bxs[3];
            *(float4*)(base + ((size_t)(t & 255) * BB + b) * C3 + c0) =
                make_float4(v0, v1, v2, v3);
        }
    }
}

// ---------------------------------------------------------------------------
// Kernel B: GRU recurrence on legacy HMMA (mma.sync m16n8k16, fp16 3-term
// split: whi*hhi + whi*hlo + wlo*hhi ~ fp32 accuracy). 128 CTAs x 32 rows,
// 256 threads (8 warps). Warp w owns units 16w..16w+15, all gates, all batch.
// smem: A = 6 fp16 matrices [128u][136k-stride] (204KB, conflict-free ldsm)
//       B = h hh/hl [128k][40b-stride] fp16 (20KB, conflict-free ldsm.trans)
// D stays in registers; gates thread-local via the mma fragment map.
// ---------------------------------------------------------------------------
#define ASTR 136                    // A row stride (halfs): (17*r)&7 distinct
#define AMAT (HID * ASTR)           // halfs per matrix = 17408
#define BSTR 40                     // B row stride (halfs): (5*k)&7 distinct
#define SM_B0 (6 * AMAT * 2)        // byte offset of B_hh = 208896
#define SM_B1 (SM_B0 + HID * BSTR * 2)  // B_hl = 219136
#define SM_TOT (SM_B1 + HID * BSTR * 2) // 229376

__global__ void __launch_bounds__(256, 1)
gru_kernel(const float* __restrict__ w_h,
           const float* __restrict__ b_h,
           const float* __restrict__ fc_w,
           const float* __restrict__ fc_b,
           float* __restrict__ out) {
    extern __shared__ char smem[];
    __half* sA = (__half*)smem;
    __half* sBhh = (__half*)(smem + SM_B0);
    __half* sBhl = (__half*)(smem + SM_B1);
    const uint32_t sb = smem_u32(smem);

    const int tid = threadIdx.x;
    const int w   = tid >> 5;
    const int L   = tid & 31;
    const int row0 = blockIdx.x * 32;
    const int uBase = 16 * w + (L >> 2);   // unit of fragment row L/4

    // ---- load + split weights into A matrices (once) ----
    for (int g = 0; g < 3; ++g) {
        __half* ah = sA + (g * 2 + 0) * AMAT;
        __half* al = sA + (g * 2 + 1) * AMAT;
        const float* wg = w_h + (size_t)g * HID * HID;
        for (int idx = tid; idx < HID * HID; idx += 256) {
            int k = idx >> 7, u = idx & 127;
            float v = wg[idx];                    // w_h[g][k][u], coalesced
            __half hi = __float2half_rn(v);
            __half lo = __float2half_rn(v - __half2float(hi));
            ah[u * ASTR + k] = hi;
            al[u * ASTR + k] = lo;
        }
    }
    // ---- zero h (B tiles) ----
    for (int i = tid; i < HID * BSTR; i += 256) { sBhh[i] = __ushort_as_half(0); sBhl[i] = __ushort_as_half(0); }
    __syncthreads();

    // ---- lane-constant ldmatrix addresses ----
    const uint32_t lrow = (L & 7) + ((L >> 3) & 1) * 8;   // row within 16
    const uint32_t lcol = (L >> 4) * 8;                   // col-half select
    uint32_t aAddr[6];
#pragma unroll
    for (int m = 0; m < 6; ++m)
        aAddr[m] = sb + (uint32_t)(m * AMAT + (16 * w + lrow) * ASTR + lcol) * 2;
    const uint32_t bAddrHH = sb + SM_B0 + (lrow * BSTR + lcol) * 2;
    const uint32_t bAddrHL = sb + SM_B1 + (lrow * BSTR + lcol) * 2;

    // ---- biases, state ----
    float bhr[2], bhz[2], bhn[2];
#pragma unroll
    for (int ui = 0; ui < 2; ++ui) {
        int u = uBase + 8 * ui;
        bhr[ui] = b_h[u];
        bhz[ui] = b_h[HID + u];
        bhn[ui] = b_h[2 * HID + u];
    }
    float hold[2][8];
#pragma unroll
    for (int ui = 0; ui < 2; ++ui)
#pragma unroll
        for (int e = 0; e < 8; ++e) hold[ui][e] = 0.0f;

    for (int t = 0; t < TT; ++t) {
        // ---- prefetch gx(t) into regs (consumed after mma loop) ----
        float pg[3][2][8];
        {
            const float* base = (t < 256) ? g_gx_lo : g_gx_hi;
            const float* gp = base + (size_t)(t & 255) * BB * C3;
#pragma unroll
            for (int g = 0; g < 3; ++g)
#pragma unroll
                for (int ui = 0; ui < 2; ++ui) {
                    int u = uBase + 8 * ui;
#pragma unroll
                    for (int e = 0; e < 8; ++e) {
                        int b = 8 * (e >> 1) + 2 * (L & 3) + (e & 1);
                        pg[g][ui][e] = __ldg(gp + (size_t)(row0 + b) * C3 + g * HID + u);
                    }
                }
        }

        // ---- MMA: acc[g][nb] = sum_k W[g]^T h ----
        float acc[3][4][4];
#pragma unroll
        for (int g = 0; g < 3; ++g)
#pragma unroll
            for (int nb = 0; nb < 4; ++nb)
#pragma unroll
                for (int i = 0; i < 4; ++i) acc[g][nb][i] = 0.0f;

#pragma unroll 2
        for (int kt = 0; kt < 8; ++kt) {
            uint32_t bh[4][2], bl[4][2];
#pragma unroll
            for (int nbp = 0; nbp < 2; ++nbp) {
                uint32_t r0, r1, r2, r3;
                ldsm4t(r0, r1, r2, r3, bAddrHH + kt * (16 * BSTR * 2) + nbp * 32);
                bh[2 * nbp][0] = r0; bh[2 * nbp][1] = r1;
                bh[2 * nbp + 1][0] = r2; bh[2 * nbp + 1][1] = r3;
                ldsm4t(r0, r1, r2, r3, bAddrHL + kt * (16 * BSTR * 2) + nbp * 32);
                bl[2 * nbp][0] = r0; bl[2 * nbp][1] = r1;
                bl[2 * nbp + 1][0] = r2; bl[2 * nbp + 1][1] = r3;
            }
#pragma unroll
            for (int g = 0; g < 3; ++g) {
                uint32_t ah0, ah1, ah2, ah3, al0, al1, al2, al3;
                ldsm4(ah0, ah1, ah2, ah3, aAddr[g * 2 + 0] + kt * 32);
                ldsm4(al0, al1, al2, al3, aAddr[g * 2 + 1] + kt * 32);
#pragma unroll
                for (int nb = 0; nb < 4; ++nb) {
                    mma16816(acc[g][nb], ah0, ah1, ah2, ah3, bh[nb][0], bh[nb][1]);
                    mma16816(acc[g][nb], ah0, ah1, ah2, ah3, bl[nb][0], bl[nb][1]);
                    mma16816(acc[g][nb], al0, al1, al2, al3, bh[nb][0], bh[nb][1]);
                }
            }
        }

        // ---- gates (thread-local). Fragment: d[2*ui+q] = (row L/4 + 8ui,
        //      col 2(L%4)+q) of tile nb -> batch b = 8nb + 2(L%4) + q ----
        float hn[2][8];
#pragma unroll
        for (int ui = 0; ui < 2; ++ui)
#pragma unroll
            for (int nb = 0; nb < 4; ++nb)
#pragma unroll
                for (int q = 0; q < 2; ++q) {
                    int e = 2 * nb + q;
                    float ar = acc[0][nb][2 * ui + q] + pg[0][ui][e] + bhr[ui];
                    float az = acc[1][nb][2 * ui + q] + pg[1][ui][e] + bhz[ui];
                    float an = acc[2][nb][2 * ui + q] + bhn[ui];
                    float rr = sig1(ar);
                    float zz = sig1(az);
                    float nn = tanh1(pg[2][ui][e] + rr * an);
                    hn[ui][e] = nn + zz * (hold[ui][e] - nn);
                    hold[ui][e] = hn[ui][e];
                }

        __syncthreads();   // all warps done reading B(t)

        // ---- write h(t+1) as fp16 hi/lo into B [k=unit][b] ----
#pragma unroll
        for (int ui = 0; ui < 2; ++ui) {
            int u = uBase + 8 * ui;
#pragma unroll
            for (int nb = 0; nb < 4; ++nb) {
                int b = 8 * nb + 2 * (L & 3);
                float v0 = hn[ui][2 * nb], v1 = hn[ui][2 * nb + 1];
                __half h0 = __float2half_rn(v0);
                __half h1 = __float2half_rn(v1);
                __half l0 = __float2half_rn(v0 - __half2float(h0));
                __half l1 = __float2half_rn(v1 - __half2float(h1));
                *(__half2*)(sBhh + u * BSTR + b) = __halves2half2(h0, h1);
                *(__half2*)(sBhl + u * BSTR + b) = __halves2half2(l0, l1);
            }
        }
        __syncthreads();   // B(t+1) visible
    }

    // ---- FC epilogue (reuse A region as fp32 h + fc_w staging) ----
    float* sH  = (float*)smem;              // [128][33]
    float* sFW = (float*)smem + HID * 33;   // [128][10]
#pragma unroll
    for (int ui = 0; ui < 2; ++ui) {
        int u = uBase + 8 * ui;
#pragma unroll
        for (int e = 0; e < 8; ++e) {
            int b = 8 * (e >> 1) + 2 * (L & 3) + (e & 1);
            sH[u * 33 + b] = hold[ui][e];
        }
    }
    for (int i = tid; i < HID * 10; i += 256) sFW[i] = fc_w[i];
    __syncthreads();
    for (int i = tid; i < 32 * 10; i += 256) {
        int lr = i / 10, col = i % 10;
        float s = fc_b[col];
#pragma unroll 8
        for (int uu = 0; uu < HID; ++uu)
            s += sH[uu * 33 + lr] * sFW[uu * 10 + col];
        out[(size_t)(row0 + lr) * 10 + col] = s;
    }
}

extern "C" void kernel_launch(void* const* d_in, const int* in_sizes, int n_in,
                              void* d_out, int out_size) {
    const float* x    = (const float*)d_in[0];
    const float* w_x  = (const float*)d_in[1];
    const float* b_x  = (const float*)d_in[2];
    const float* w_h  = (const float*)d_in[3];
    const float* b_h  = (const float*)d_in[4];
    const float* fc_w = (const float*)d_in[5];
    const float* fc_b = (const float*)d_in[6];
    float* out = (float*)d_out;

    const int smemA = (INP * C3 + 32 * INP) * sizeof(float);
    cudaFuncSetAttribute(gx_kernel,  cudaFuncAttributeMaxDynamicSharedMemorySize, smemA);
    cudaFuncSetAttribute(gru_kernel, cudaFuncAttributeMaxDynamicSharedMemorySize, SM_TOT);

    gx_kernel<<<BB, 384, smemA>>>(x, w_x, b_x);
    gru_kernel<<<128, 256, SM_TOT>>>(w_h, b_h, fc_w, fc_b, out);
}